// round 1
// baseline (speedup 1.0000x reference)
#include <cuda_runtime.h>
#include <math.h>

#define BATCH 4096
#define NNEG 64
#define DIM 128
#define HID 512
#define MARGINF 24.0f
#define MROWS 32

// Scratch (allocation-free rule: __device__ globals). Written non-atomically
// each launch -> graph-replay safe, no zeroing needed.
__device__ float g_conf[BATCH];
__device__ float g_dpos[BATCH];
__device__ float g_negsp[BATCH];   // sum over negs of softplus(d_neg - MARGIN)

__device__ __forceinline__ float warp_sum(float v) {
#pragma unroll
    for (int o = 16; o; o >>= 1) v += __shfl_xor_sync(0xffffffffu, v, o);
    return v;
}

// stable softplus(z) = max(z,0) + log1p(exp(-|z|));  -log_sigmoid(x) = softplus(-x)
__device__ __forceinline__ float softplusf(float z) {
    return fmaxf(z, 0.f) + log1pf(expf(-fabsf(z)));
}

// ---------------------------------------------------------------------------
// Kernel 1: positive pass. 32 rows per block, 512 threads.
//  - gather h,r,t rows, build diff tile (k-major in shared, padded to 36)
//  - d_pos = sum |diff|
//  - fused MLP: thread j owns hidden column j; acc over 32 rows; W1 read once
//    per block (coalesced), diff read as broadcast float4 LDS.
//  - epilogue: relu, *W2[j], cross-thread reduce per row -> conf = sigmoid.
// ---------------------------------------------------------------------------
__global__ __launch_bounds__(512, 1) void mlp_pos_kernel(
    const int* __restrict__ pos, const float* __restrict__ ent,
    const float* __restrict__ rel, const float* __restrict__ W1,
    const float* __restrict__ b1, const float* __restrict__ W2,
    const float* __restrict__ b2)
{
    __shared__ float shT[DIM][36];      // [k][row], pad 36 (144B => float4-aligned rows)
    __shared__ int   sh_idx[MROWS][3];
    __shared__ float sh_part[16][MROWS];

    const int tid  = threadIdx.x;
    const int lane = tid & 31;
    const int wid  = tid >> 5;
    const int row0 = blockIdx.x * MROWS;

    if (tid < MROWS * 3)
        sh_idx[tid / 3][tid % 3] = pos[(row0 + tid / 3) * 3 + (tid % 3)];
    __syncthreads();

    // gather + diff: consecutive tid -> consecutive k (coalesced 512B per row)
#pragma unroll
    for (int s = tid; s < MROWS * DIM; s += 512) {
        int row = s >> 7, k = s & 127;
        size_t h = (size_t)sh_idx[row][0];
        int    r = sh_idx[row][1];
        size_t t = (size_t)sh_idx[row][2];
        shT[k][row] = ent[h * DIM + k] + rel[(size_t)r * DIM + k] - ent[t * DIM + k];
    }
    __syncthreads();

    // d_pos: warp w handles rows 2w, 2w+1
#pragma unroll
    for (int rr = 0; rr < 2; rr++) {
        int row = wid * 2 + rr;
        float s = 0.f;
#pragma unroll
        for (int kk = 0; kk < 4; kk++) s += fabsf(shT[lane + kk * 32][row]);
        s = warp_sum(s);
        if (lane == 0) g_dpos[row0 + row] = s;
    }

    // GEMM: column j = tid, 32 row-accumulators
    float acc[MROWS];
#pragma unroll
    for (int r = 0; r < MROWS; r++) acc[r] = 0.f;
    const int j = tid;

#pragma unroll 4
    for (int k = 0; k < DIM; k++) {
        float w = W1[k * HID + j];
#pragma unroll
        for (int q = 0; q < MROWS / 4; q++) {
            float4 d4 = *(const float4*)&shT[k][q * 4];   // broadcast LDS.128
            acc[q * 4 + 0] = fmaf(d4.x, w, acc[q * 4 + 0]);
            acc[q * 4 + 1] = fmaf(d4.y, w, acc[q * 4 + 1]);
            acc[q * 4 + 2] = fmaf(d4.z, w, acc[q * 4 + 2]);
            acc[q * 4 + 3] = fmaf(d4.w, w, acc[q * 4 + 3]);
        }
    }

    const float bj = b1[j], w2 = W2[j];
#pragma unroll
    for (int r = 0; r < MROWS; r++) acc[r] = fmaxf(acc[r] + bj, 0.f) * w2;

    // reduce 512 threads -> 1 logit per row
#pragma unroll
    for (int r = 0; r < MROWS; r++) {
        float v = warp_sum(acc[r]);
        if (lane == 0) sh_part[wid][r] = v;
    }
    __syncthreads();
    if (tid < MROWS) {
        float s = b2[0];
#pragma unroll
        for (int w = 0; w < 16; w++) s += sh_part[w][tid];
        g_conf[row0 + tid] = 1.f / (1.f + expf(-s));
    }
}

// ---------------------------------------------------------------------------
// Kernel 2: negative pass. One block per batch row b, 8 warps, 8 negs/warp.
// One warp per triple: 32 lanes x float4 = coalesced 512B row gathers.
// ---------------------------------------------------------------------------
__global__ __launch_bounds__(256, 8) void neg_kernel(
    const int* __restrict__ negt, const float* __restrict__ ent,
    const float* __restrict__ rel)
{
    const int b    = blockIdx.x;
    const int lane = threadIdx.x & 31;
    const int wid  = threadIdx.x >> 5;
    __shared__ float sh[8];

    float local = 0.f;
#pragma unroll
    for (int n = wid; n < NNEG; n += 8) {
        int base = (b * NNEG + n) * 3;
        int hi = __ldg(negt + base);
        int ri = __ldg(negt + base + 1);
        int ti = __ldg(negt + base + 2);
        float4 a  = __ldg((const float4*)(ent + (size_t)hi * DIM) + lane);
        float4 rr = __ldg((const float4*)(rel + (size_t)ri * DIM) + lane);
        float4 c  = __ldg((const float4*)(ent + (size_t)ti * DIM) + lane);
        float s = fabsf(a.x + rr.x - c.x) + fabsf(a.y + rr.y - c.y)
                + fabsf(a.z + rr.z - c.z) + fabsf(a.w + rr.w - c.w);
        s = warp_sum(s);
        if (lane == 0) local += softplusf(s - MARGINF);
    }
    if (lane == 0) sh[wid] = local;
    __syncthreads();
    if (threadIdx.x == 0) {
        float t = 0.f;
#pragma unroll
        for (int w = 0; w < 8; w++) t += sh[w];
        g_negsp[b] = t;
    }
}

// ---------------------------------------------------------------------------
// Kernel 3: final combine + scalar reduce (double accumulation).
// ---------------------------------------------------------------------------
__global__ __launch_bounds__(512, 1) void final_kernel(float* __restrict__ out)
{
    __shared__ double sh[16];
    const int tid = threadIdx.x;
    double local = 0.0;
    for (int i = tid; i < BATCH; i += 512) {
        float pt = softplusf(g_dpos[i] - MARGINF);     // -log_sigmoid(M - d_pos)
        float nt = -g_negsp[i] * (1.f / NNEG);         // mean log_sigmoid(M - d_neg)
        local += (double)(g_conf[i] * (pt + nt));
    }
#pragma unroll
    for (int o = 16; o; o >>= 1) local += __shfl_xor_sync(0xffffffffu, local, o);
    const int lane = tid & 31, wid = tid >> 5;
    if (lane == 0) sh[wid] = local;
    __syncthreads();
    if (tid < 16) {
        double v = sh[tid];
#pragma unroll
        for (int o = 8; o; o >>= 1) v += __shfl_xor_sync(0x0000ffffu, v, o);
        if (tid == 0) out[0] = (float)v;
    }
}

// ---------------------------------------------------------------------------
extern "C" void kernel_launch(void* const* d_in, const int* in_sizes, int n_in,
                              void* d_out, int out_size)
{
    const int* pos = (const int*)d_in[0];
    const int* neg = (const int*)d_in[1];
    // negative_sample_size may or may not be materialized as input[2]
    const int o = (n_in >= 9) ? 1 : 0;
    const float* ent = (const float*)d_in[2 + o];
    const float* rel = (const float*)d_in[3 + o];
    const float* W1  = (const float*)d_in[4 + o];
    const float* b1  = (const float*)d_in[5 + o];
    const float* W2  = (const float*)d_in[6 + o];
    const float* b2  = (const float*)d_in[7 + o];
    float* out = (float*)d_out;

    mlp_pos_kernel<<<BATCH / MROWS, 512>>>(pos, ent, rel, W1, b1, W2, b2);
    neg_kernel<<<BATCH, 256>>>(neg, ent, rel);
    final_kernel<<<1, 512>>>(out);
}